// round 13
// baseline (speedup 1.0000x reference)
#include <cuda_runtime.h>
#include <cuda_bf16.h>
#include <stdint.h>
#include <math.h>

// ---------------------------------------------------------------------------
// SwinIRBlock: LN1 -> shifted-window MSA (rel-pos bias + shift mask) -> proj
//              + residual -> LN2 -> MLP(GELU) + residual
// GEMMs: mma.sync tf32, 3-term split precomputed at staging, hi/lo packed
// as uint2 in smem (one LDS.64 feeds both MMA operands).
// ---------------------------------------------------------------------------

#define TOKENS   262144          // B*H*W
#define CDIM     192
#define QKVDIM   576
#define MLPDIM   768
#define NWIN     4096            // B * 256
#define HEADS    6
#define HD       32
#define SCALE    0.17677669529663687f   // 32^-0.5

// ---------------- scratch (static device arrays; no allocation) ------------
__device__ float g_ln  [ (size_t)TOKENS * CDIM   ];
__device__ float g_qkv [ (size_t)TOKENS * QKVDIM ];
__device__ float g_attn[ (size_t)TOKENS * CDIM   ];
__device__ float g_h   [ (size_t)TOKENS * CDIM   ];
__device__ float g_m1  [ (size_t)TOKENS * MLPDIM ];

// window-ordered row r -> token index (cyclic shift -4,-4 gather; same map is
// the scatter for window-reverse + roll(+4,+4))
__device__ __forceinline__ int map_shift_row(int r) {
    int win = r >> 6, n = r & 63;
    int b  = win >> 8;
    int wi = win & 255;
    int wh = wi >> 4, ww = wi & 15;
    int hh = (wh << 3) + (n >> 3);
    int wp = (ww << 3) + (n & 7);
    int hs = (hh + 4) & 127;
    int ws = (wp + 4) & 127;
    return (b << 14) + (hs << 7) + ws;
}

// ---------------------------- LayerNorm ------------------------------------
__global__ void __launch_bounds__(256)
ln_kernel(const float* __restrict__ x, const float* __restrict__ g,
          const float* __restrict__ b, float* __restrict__ y)
{
    int token = blockIdx.x * 8 + (threadIdx.x >> 5);
    int lane  = threadIdx.x & 31;
    const float* xp = x + (size_t)token * CDIM;

    float v[6];
    float s = 0.f;
#pragma unroll
    for (int i = 0; i < 6; i++) { v[i] = xp[lane + i * 32]; s += v[i]; }
#pragma unroll
    for (int o = 16; o > 0; o >>= 1) s += __shfl_xor_sync(0xffffffffu, s, o);
    float mean = s * (1.f / 192.f);

    float s2 = 0.f;
#pragma unroll
    for (int i = 0; i < 6; i++) { float d = v[i] - mean; s2 += d * d; }
#pragma unroll
    for (int o = 16; o > 0; o >>= 1) s2 += __shfl_xor_sync(0xffffffffu, s2, o);
    float rs = rsqrtf(s2 * (1.f / 192.f) + 1e-5f);

    float* yp = y + (size_t)token * CDIM;
#pragma unroll
    for (int i = 0; i < 6; i++) {
        int c = lane + i * 32;
        yp[c] = (v[i] - mean) * rs * g[c] + b[c];
    }
}

// ------------------------- TF32 split helpers ------------------------------
__device__ __forceinline__ uint2 tf32_split2(float x) {
    unsigned int h;
    asm("cvt.rna.tf32.f32 %0, %1;" : "=r"(h) : "f"(x));
    float lf = x - __uint_as_float(h);
    unsigned int l;
    asm("cvt.rna.tf32.f32 %0, %1;" : "=r"(l) : "f"(lf));
    return make_uint2(h, l);
}

#define MMA_TF32(d, a0, a1, a2, a3, b0, b1)                                   \
    asm volatile("mma.sync.aligned.m16n8k8.row.col.f32.tf32.tf32.f32 "        \
                 "{%0,%1,%2,%3}, {%4,%5,%6,%7}, {%8,%9}, {%0,%1,%2,%3};"      \
                 : "+f"(d[0]), "+f"(d[1]), "+f"(d[2]), "+f"(d[3])             \
                 : "r"(a0), "r"(a1), "r"(a2), "r"(a3), "r"(b0), "r"(b1))

// XOR swizzle: decorrelates the k-quad from the column; (k>>2) is constant
// per fragment-load instruction so loads stay conflict-free.
#define SW(k, c) ((c) ^ ((((k) >> 2) & 3) << 3))

// ------------------------------ GEMM ---------------------------------------
// C[m,n] = sum_k A[row(m),k] * W[n,k] + bias[n]  (+ epilogue)
// 256 threads = 8 warps (4x2); BM=128 BN=64 BK=16; warp tile 32x32.
#define AM_DIRECT 0
#define AM_SHIFT  1
#define EPI_BIAS        0
#define EPI_GELU        1
#define EPI_RES_SCATTER 2
#define EPI_RES_DIRECT  3

template<int Kdim, int Ndim, int AMap, int Epi>
__global__ void __launch_bounds__(256, 2)
gemm_kernel(const float* __restrict__ A, const float* __restrict__ W,
            const float* __restrict__ bias, const float* __restrict__ res,
            float* __restrict__ C)
{
    constexpr int BM = 128, BN = 64, BK = 16;
    __shared__ uint2 Ahl[BK][BM + 4];   // .x = tf32 hi, .y = tf32 lo
    __shared__ uint2 Whl[BK][BN + 4];

    const int tid  = threadIdx.x;
    const int lane = tid & 31;
    const int warp = tid >> 5;
    const int wm   = warp >> 1;     // 0..3  (m direction, 32 rows each)
    const int wn   = warp & 1;      // 0..1  (n direction, 32 cols each)
    const int m0   = blockIdx.y * BM;
    const int n0   = blockIdx.x * BN;

    // global loaders: A 128x16 = 512 float4 -> 2/thread; W 64x16 = 256 -> 1/thread
    const float* aptr[2]; int arow[2], akq[2];
#pragma unroll
    for (int i = 0; i < 2; i++) {
        int f = tid + i * 256;
        arow[i] = f >> 2; akq[i] = f & 3;
        int gr = m0 + arow[i];
        if (AMap == AM_SHIFT) gr = map_shift_row(gr);
        aptr[i] = A + (size_t)gr * Kdim + akq[i] * 4;
    }
    const int wrow = tid >> 2, wkq = tid & 3;
    const float* wptr = W + (size_t)(n0 + wrow) * Kdim + wkq * 4;

    float acc[2][4][4] = {};

    float4 av[2], wv;
#pragma unroll
    for (int i = 0; i < 2; i++) av[i] = *reinterpret_cast<const float4*>(aptr[i]);
    wv = *reinterpret_cast<const float4*>(wptr);

    const int r  = lane >> 2;
    const int kq = lane & 3;

    for (int kt = 0; kt < Kdim; kt += BK) {
        // stage current tile, splitting to tf32 hi/lo ONCE per element
#pragma unroll
        for (int i = 0; i < 2; i++) {
            float vv[4] = {av[i].x, av[i].y, av[i].z, av[i].w};
#pragma unroll
            for (int j = 0; j < 4; j++) {
                int k = akq[i] * 4 + j;
                Ahl[k][SW(k, arow[i])] = tf32_split2(vv[j]);
            }
        }
        {
            float vv[4] = {wv.x, wv.y, wv.z, wv.w};
#pragma unroll
            for (int j = 0; j < 4; j++) {
                int k = wkq * 4 + j;
                Whl[k][SW(k, wrow)] = tf32_split2(vv[j]);
            }
        }
        __syncthreads();

        // prefetch next tile into registers (hidden behind MMA work)
        if (kt + BK < Kdim) {
#pragma unroll
            for (int i = 0; i < 2; i++)
                av[i] = *reinterpret_cast<const float4*>(aptr[i] + kt + BK);
            wv = *reinterpret_cast<const float4*>(wptr + kt + BK);
        }

#pragma unroll
        for (int ks = 0; ks < 2; ks++) {
            const int kA = ks * 8 + kq;
            const int kB = ks * 8 + 4 + kq;
            uint2 a[2][4], b[4][2];
#pragma unroll
            for (int mt = 0; mt < 2; mt++) {
                int mb = wm * 32 + mt * 16 + r;
                a[mt][0] = Ahl[kA][SW(kA, mb)];
                a[mt][1] = Ahl[kA][SW(kA, mb + 8)];
                a[mt][2] = Ahl[kB][SW(kB, mb)];
                a[mt][3] = Ahl[kB][SW(kB, mb + 8)];
            }
#pragma unroll
            for (int nt = 0; nt < 4; nt++) {
                int nb = wn * 32 + nt * 8 + r;
                b[nt][0] = Whl[kA][SW(kA, nb)];
                b[nt][1] = Whl[kB][SW(kB, nb)];
            }
#pragma unroll
            for (int mt = 0; mt < 2; mt++)
#pragma unroll
                for (int nt = 0; nt < 4; nt++) {
                    MMA_TF32(acc[mt][nt], a[mt][0].x, a[mt][1].x, a[mt][2].x, a[mt][3].x,
                             b[nt][0].x, b[nt][1].x);
                    MMA_TF32(acc[mt][nt], a[mt][0].x, a[mt][1].x, a[mt][2].x, a[mt][3].x,
                             b[nt][0].y, b[nt][1].y);
                    MMA_TF32(acc[mt][nt], a[mt][0].y, a[mt][1].y, a[mt][2].y, a[mt][3].y,
                             b[nt][0].x, b[nt][1].x);
                }
        }
        __syncthreads();
    }

    // ----------------------------- epilogue --------------------------------
#pragma unroll
    for (int nt = 0; nt < 4; nt++) {
        const int col = n0 + wn * 32 + nt * 8 + (lane & 3) * 2;
        const float b0v = bias[col], b1v = bias[col + 1];
#pragma unroll
        for (int mt = 0; mt < 2; mt++) {
#pragma unroll
            for (int half = 0; half < 2; half++) {
                int m = m0 + wm * 32 + mt * 16 + (lane >> 2) + half * 8;
                float v0 = acc[mt][nt][half * 2 + 0] + b0v;
                float v1 = acc[mt][nt][half * 2 + 1] + b1v;
                if (Epi == EPI_GELU) {
                    v0 = 0.5f * v0 * (1.f + erff(v0 * 0.70710678118654752f));
                    v1 = 0.5f * v1 * (1.f + erff(v1 * 0.70710678118654752f));
                }
                int outrow = (Epi == EPI_RES_SCATTER) ? map_shift_row(m) : m;
                float* cp = C + (size_t)outrow * Ndim + col;
                if (Epi == EPI_RES_SCATTER || Epi == EPI_RES_DIRECT) {
                    float2 rr = *reinterpret_cast<const float2*>(
                        res + (size_t)outrow * Ndim + col);
                    v0 += rr.x; v1 += rr.y;
                }
                *reinterpret_cast<float2*>(cp) = make_float2(v0, v1);
            }
        }
    }
}

// --------------------------- Attention -------------------------------------
// one 64-thread block per (window, head); thread = query row n
__global__ void __launch_bounds__(64)
attn_kernel(const float* __restrict__ qkv, const float* __restrict__ rpb,
            float* __restrict__ out)
{
    __shared__ float Ksm[64][36];
    __shared__ float Vsm[64][36];
    __shared__ float bsm[1350];      // 225 * 6

    const int head = blockIdx.x % HEADS;
    const int win  = blockIdx.x / HEADS;
    const int n    = threadIdx.x;

    for (int i = n; i < 1350; i += 64) bsm[i] = rpb[i];

    const float* base = qkv + (size_t)win * 64 * QKVDIM;
    const float* qp = base + n * QKVDIM + head * HD;
    const float* kp = qp + CDIM;
    const float* vp = qp + 2 * CDIM;

    float q[32];
#pragma unroll
    for (int d4 = 0; d4 < 8; d4++) {
        float4 kv = *reinterpret_cast<const float4*>(kp + d4 * 4);
        Ksm[n][d4 * 4 + 0] = kv.x; Ksm[n][d4 * 4 + 1] = kv.y;
        Ksm[n][d4 * 4 + 2] = kv.z; Ksm[n][d4 * 4 + 3] = kv.w;
        float4 vv = *reinterpret_cast<const float4*>(vp + d4 * 4);
        Vsm[n][d4 * 4 + 0] = vv.x; Vsm[n][d4 * 4 + 1] = vv.y;
        Vsm[n][d4 * 4 + 2] = vv.z; Vsm[n][d4 * 4 + 3] = vv.w;
        float4 qq = *reinterpret_cast<const float4*>(qp + d4 * 4);
        q[d4 * 4 + 0] = qq.x * SCALE; q[d4 * 4 + 1] = qq.y * SCALE;
        q[d4 * 4 + 2] = qq.z * SCALE; q[d4 * 4 + 3] = qq.w * SCALE;
    }
    __syncthreads();

    const int wi = win & 255, wh = wi >> 4, ww = wi & 15;
    const int i1 = n >> 3, j1 = n & 7;
    const int rh1 = (wh == 15) ? ((i1 < 4) ? 1 : 2) : 0;
    const int rw1 = (ww == 15) ? ((j1 < 4) ? 1 : 2) : 0;

    float s[64];
#pragma unroll
    for (int m = 0; m < 64; m++) {
        float dot = 0.f;
#pragma unroll
        for (int d4 = 0; d4 < 8; d4++) {
            float4 kk = *reinterpret_cast<const float4*>(&Ksm[m][d4 * 4]);
            dot = fmaf(q[d4 * 4 + 0], kk.x, dot);
            dot = fmaf(q[d4 * 4 + 1], kk.y, dot);
            dot = fmaf(q[d4 * 4 + 2], kk.z, dot);
            dot = fmaf(q[d4 * 4 + 3], kk.w, dot);
        }
        const int i2 = m >> 3, j2 = m & 7;
        float bias = bsm[((i1 - i2 + 7) * 15 + (j1 - j2 + 7)) * HEADS + head];
        const int rh2 = (wh == 15) ? ((i2 < 4) ? 1 : 2) : 0;
        const int rw2 = (ww == 15) ? ((j2 < 4) ? 1 : 2) : 0;
        float msk = (rh1 == rh2 && rw1 == rw2) ? 0.f : -100.f;
        s[m] = dot + bias + msk;
    }

    float mx = -1e30f;
#pragma unroll
    for (int m = 0; m < 64; m++) mx = fmaxf(mx, s[m]);
    float sum = 0.f;
#pragma unroll
    for (int m = 0; m < 64; m++) { s[m] = __expf(s[m] - mx); sum += s[m]; }
    float inv = 1.f / sum;

    float o[32] = {};
#pragma unroll
    for (int m = 0; m < 64; m++) {
        float p = s[m] * inv;
#pragma unroll
        for (int d4 = 0; d4 < 8; d4++) {
            float4 vv = *reinterpret_cast<const float4*>(&Vsm[m][d4 * 4]);
            o[d4 * 4 + 0] = fmaf(p, vv.x, o[d4 * 4 + 0]);
            o[d4 * 4 + 1] = fmaf(p, vv.y, o[d4 * 4 + 1]);
            o[d4 * 4 + 2] = fmaf(p, vv.z, o[d4 * 4 + 2]);
            o[d4 * 4 + 3] = fmaf(p, vv.w, o[d4 * 4 + 3]);
        }
    }

    float* op = out + (size_t)(win * 64 + n) * CDIM + head * HD;
#pragma unroll
    for (int d4 = 0; d4 < 8; d4++)
        *reinterpret_cast<float4*>(op + d4 * 4) =
            make_float4(o[d4 * 4 + 0], o[d4 * 4 + 1], o[d4 * 4 + 2], o[d4 * 4 + 3]);
}

// ---------------------------------------------------------------------------
extern "C" void kernel_launch(void* const* d_in, const int* in_sizes, int n_in,
                              void* d_out, int out_size)
{
    const float* x       = (const float*)d_in[0];
    const float* norm1_g = (const float*)d_in[1];
    const float* norm1_b = (const float*)d_in[2];
    const float* qkv_w   = (const float*)d_in[3];
    const float* qkv_b   = (const float*)d_in[4];
    const float* proj_w  = (const float*)d_in[5];
    const float* proj_b  = (const float*)d_in[6];
    const float* rpb     = (const float*)d_in[7];
    const float* norm2_g = (const float*)d_in[8];
    const float* norm2_b = (const float*)d_in[9];
    const float* fc1_w   = (const float*)d_in[10];
    const float* fc1_b   = (const float*)d_in[11];
    const float* fc2_w   = (const float*)d_in[12];
    const float* fc2_b   = (const float*)d_in[13];
    float* out = (float*)d_out;

    float *p_ln, *p_qkv, *p_attn, *p_h, *p_m1;
    cudaGetSymbolAddress((void**)&p_ln,   g_ln);
    cudaGetSymbolAddress((void**)&p_qkv,  g_qkv);
    cudaGetSymbolAddress((void**)&p_attn, g_attn);
    cudaGetSymbolAddress((void**)&p_h,    g_h);
    cudaGetSymbolAddress((void**)&p_m1,   g_m1);

    const dim3 gemmBlk(256);
    const dim3 gridQKV(QKVDIM / 64, TOKENS / 128);
    const dim3 gridC  (CDIM   / 64, TOKENS / 128);
    const dim3 gridM  (MLPDIM / 64, TOKENS / 128);

    // 1. LN1
    ln_kernel<<<TOKENS / 8, 256>>>(x, norm1_g, norm1_b, p_ln);
    // 2. QKV gemm with shifted-window row gather
    gemm_kernel<CDIM, QKVDIM, AM_SHIFT, EPI_BIAS>
        <<<gridQKV, gemmBlk>>>(p_ln, qkv_w, qkv_b, nullptr, p_qkv);
    // 3. windowed attention (bias + shift mask + softmax)
    attn_kernel<<<NWIN * HEADS, 64>>>(p_qkv, rpb, p_attn);
    // 4. proj gemm; scatter rows back (window reverse + roll) + shortcut residual
    gemm_kernel<CDIM, CDIM, AM_DIRECT, EPI_RES_SCATTER>
        <<<gridC, gemmBlk>>>(p_attn, proj_w, proj_b, x, p_h);
    // 5. LN2
    ln_kernel<<<TOKENS / 8, 256>>>(p_h, norm2_g, norm2_b, p_ln);
    // 6. FC1 + exact GELU
    gemm_kernel<CDIM, MLPDIM, AM_DIRECT, EPI_GELU>
        <<<gridM, gemmBlk>>>(p_ln, fc1_w, fc1_b, nullptr, p_m1);
    // 7. FC2 + residual h  -> d_out
    gemm_kernel<MLPDIM, CDIM, AM_DIRECT, EPI_RES_DIRECT>
        <<<gridC, gemmBlk>>>(p_m1, fc2_w, fc2_b, p_h, out);
}

// round 15
// speedup vs baseline: 1.5444x; 1.5444x over previous
#include <cuda_runtime.h>
#include <cuda_bf16.h>
#include <stdint.h>
#include <math.h>

// ---------------------------------------------------------------------------
// SwinIRBlock: LN1 -> shifted-window MSA (rel-pos bias + shift mask) -> proj
//              + residual -> LN2 -> MLP(GELU) + residual
// GEMMs: mma.sync.m16n8k16.bf16 with 3-term hi/lo split (fp32-class accuracy),
// split precomputed at staging, hi/lo bf16x2 pairs packed per uint2, smem
// double-buffered (one barrier per k16 tile).
// ---------------------------------------------------------------------------

#define TOKENS   262144          // B*H*W
#define CDIM     192
#define QKVDIM   576
#define MLPDIM   768
#define NWIN     4096            // B * 256
#define HEADS    6
#define HD       32
#define SCALE    0.17677669529663687f   // 32^-0.5

// ---------------- scratch (static device arrays; no allocation) ------------
__device__ float g_ln  [ (size_t)TOKENS * CDIM   ];
__device__ float g_qkv [ (size_t)TOKENS * QKVDIM ];
__device__ float g_attn[ (size_t)TOKENS * CDIM   ];
__device__ float g_h   [ (size_t)TOKENS * CDIM   ];
__device__ float g_m1  [ (size_t)TOKENS * MLPDIM ];

// window-ordered row r -> token index (cyclic shift -4,-4 gather; same map is
// the scatter for window-reverse + roll(+4,+4))
__device__ __forceinline__ int map_shift_row(int r) {
    int win = r >> 6, n = r & 63;
    int b  = win >> 8;
    int wi = win & 255;
    int wh = wi >> 4, ww = wi & 15;
    int hh = (wh << 3) + (n >> 3);
    int wp = (ww << 3) + (n & 7);
    int hs = (hh + 4) & 127;
    int ws = (wp + 4) & 127;
    return (b << 14) + (hs << 7) + ws;
}

// ---------------------------- LayerNorm ------------------------------------
__global__ void __launch_bounds__(256)
ln_kernel(const float* __restrict__ x, const float* __restrict__ g,
          const float* __restrict__ b, float* __restrict__ y)
{
    int token = blockIdx.x * 8 + (threadIdx.x >> 5);
    int lane  = threadIdx.x & 31;
    const float* xp = x + (size_t)token * CDIM;

    float v[6];
    float s = 0.f;
#pragma unroll
    for (int i = 0; i < 6; i++) { v[i] = xp[lane + i * 32]; s += v[i]; }
#pragma unroll
    for (int o = 16; o > 0; o >>= 1) s += __shfl_xor_sync(0xffffffffu, s, o);
    float mean = s * (1.f / 192.f);

    float s2 = 0.f;
#pragma unroll
    for (int i = 0; i < 6; i++) { float d = v[i] - mean; s2 += d * d; }
#pragma unroll
    for (int o = 16; o > 0; o >>= 1) s2 += __shfl_xor_sync(0xffffffffu, s2, o);
    float rs = rsqrtf(s2 * (1.f / 192.f) + 1e-5f);

    float* yp = y + (size_t)token * CDIM;
#pragma unroll
    for (int i = 0; i < 6; i++) {
        int c = lane + i * 32;
        yp[c] = (v[i] - mean) * rs * g[c] + b[c];
    }
}

// ------------------------- BF16 split helpers -------------------------------
// Pack two consecutive-k floats into (hi bf16x2, lo bf16x2). Even k in the low
// half of each bf16x2 (matches m16n8k16 fragment layout).
__device__ __forceinline__ uint2 bf16_split_pair(float v0, float v1) {
    __nv_bfloat162 h = __floats2bfloat162_rn(v0, v1);
    float l0 = v0 - __bfloat162float(h.x);
    float l1 = v1 - __bfloat162float(h.y);
    __nv_bfloat162 l = __floats2bfloat162_rn(l0, l1);
    uint2 r;
    r.x = *reinterpret_cast<unsigned int*>(&h);
    r.y = *reinterpret_cast<unsigned int*>(&l);
    return r;
}

#define MMA_BF16(d, a0, a1, a2, a3, b0, b1)                                   \
    asm volatile("mma.sync.aligned.m16n8k16.row.col.f32.bf16.bf16.f32 "       \
                 "{%0,%1,%2,%3}, {%4,%5,%6,%7}, {%8,%9}, {%0,%1,%2,%3};"      \
                 : "+f"(d[0]), "+f"(d[1]), "+f"(d[2]), "+f"(d[3])             \
                 : "r"(a0), "r"(a1), "r"(a2), "r"(a3), "r"(b0), "r"(b1))

// ------------------------------ GEMM ---------------------------------------
// C[m,n] = sum_k A[row(m),k] * W[n,k] + bias[n]  (+ epilogue)
// 256 threads = 8 warps (4x2); BM=128 BN=64, k-step 16; warp tile 32x32.
// Smem holds bf16 hi/lo planes packed as uint2 per (k-pair, row), double-buffered.
// Row stride (BM+4 / BN+4 uint2) == 8 mod 32 banks -> fragment loads conflict-free.
#define AM_DIRECT 0
#define AM_SHIFT  1
#define EPI_BIAS        0
#define EPI_GELU        1
#define EPI_RES_SCATTER 2
#define EPI_RES_DIRECT  3

template<int Kdim, int Ndim, int AMap, int Epi>
__global__ void __launch_bounds__(256, 2)
gemm_kernel(const float* __restrict__ A, const float* __restrict__ W,
            const float* __restrict__ bias, const float* __restrict__ res,
            float* __restrict__ C)
{
    constexpr int BM = 128, BN = 64;
    constexpr int NT = Kdim / 16;           // k16 tiles
    __shared__ uint2 Ahl[2][8][BM + 4];     // [buf][k-pair][m] = (hi bf16x2, lo bf16x2)
    __shared__ uint2 Whl[2][8][BN + 4];

    const int tid  = threadIdx.x;
    const int lane = tid & 31;
    const int warp = tid >> 5;
    const int wm   = warp >> 1;     // 0..3  (m direction, 32 rows each)
    const int wn   = warp & 1;      // 0..1  (n direction, 32 cols each)
    const int m0   = blockIdx.y * BM;
    const int n0   = blockIdx.x * BN;

    // global loaders: A 128x16 = 512 float4 -> 2/thread; W 64x16 = 256 -> 1/thread
    const float* aptr[2]; int arow[2], akq[2];
#pragma unroll
    for (int i = 0; i < 2; i++) {
        int f = tid + i * 256;
        arow[i] = f >> 2; akq[i] = f & 3;        // akq = k-quad (4 floats = 2 k-pairs)
        int gr = m0 + arow[i];
        if (AMap == AM_SHIFT) gr = map_shift_row(gr);
        aptr[i] = A + (size_t)gr * Kdim + akq[i] * 4;
    }
    const int wrow = tid >> 2, wkq = tid & 3;
    const float* wptr = W + (size_t)(n0 + wrow) * Kdim + wkq * 4;

    float acc[2][4][4] = {};

    float4 av[2], wv;

    // ---- prologue: tile 0 -> buf 0; prefetch tile 1 into regs -------------
#pragma unroll
    for (int i = 0; i < 2; i++) av[i] = *reinterpret_cast<const float4*>(aptr[i]);
    wv = *reinterpret_cast<const float4*>(wptr);
#pragma unroll
    for (int i = 0; i < 2; i++) {
        Ahl[0][2 * akq[i] + 0][arow[i]] = bf16_split_pair(av[i].x, av[i].y);
        Ahl[0][2 * akq[i] + 1][arow[i]] = bf16_split_pair(av[i].z, av[i].w);
    }
    Whl[0][2 * wkq + 0][wrow] = bf16_split_pair(wv.x, wv.y);
    Whl[0][2 * wkq + 1][wrow] = bf16_split_pair(wv.z, wv.w);
    if (NT > 1) {
#pragma unroll
        for (int i = 0; i < 2; i++)
            av[i] = *reinterpret_cast<const float4*>(aptr[i] + 16);
        wv = *reinterpret_cast<const float4*>(wptr + 16);
    }

    const int g = lane >> 2;       // row-group / B-col within fragment
    const int t = lane & 3;        // k-pair selector

    for (int it = 0; it < NT; ++it) {
        const int cur = it & 1;
        __syncthreads();

        // stage prefetched tile (it+1) into the other buffer
        if (it + 1 < NT) {
            const int nxt = cur ^ 1;
#pragma unroll
            for (int i = 0; i < 2; i++) {
                Ahl[nxt][2 * akq[i] + 0][arow[i]] = bf16_split_pair(av[i].x, av[i].y);
                Ahl[nxt][2 * akq[i] + 1][arow[i]] = bf16_split_pair(av[i].z, av[i].w);
            }
            Whl[nxt][2 * wkq + 0][wrow] = bf16_split_pair(wv.x, wv.y);
            Whl[nxt][2 * wkq + 1][wrow] = bf16_split_pair(wv.z, wv.w);
        }
        // prefetch tile (it+2) into registers
        if (it + 2 < NT) {
            const int kt = (it + 2) * 16;
#pragma unroll
            for (int i = 0; i < 2; i++)
                av[i] = *reinterpret_cast<const float4*>(aptr[i] + kt);
            wv = *reinterpret_cast<const float4*>(wptr + kt);
        }

        // ---- compute current buffer: 16 LDS.64 + 24 MMA per warp ----------
        uint2 a[2][4], b[4][2];
#pragma unroll
        for (int mt = 0; mt < 2; mt++) {
            int mb = wm * 32 + mt * 16 + g;
            a[mt][0] = Ahl[cur][t    ][mb];       // rows g,   k-pair t
            a[mt][1] = Ahl[cur][t    ][mb + 8];   // rows g+8, k-pair t
            a[mt][2] = Ahl[cur][t + 4][mb];       // rows g,   k-pair t+4
            a[mt][3] = Ahl[cur][t + 4][mb + 8];   // rows g+8, k-pair t+4
        }
#pragma unroll
        for (int nt = 0; nt < 4; nt++) {
            int nb = wn * 32 + nt * 8 + g;
            b[nt][0] = Whl[cur][t    ][nb];
            b[nt][1] = Whl[cur][t + 4][nb];
        }
#pragma unroll
        for (int mt = 0; mt < 2; mt++)
#pragma unroll
            for (int nt = 0; nt < 4; nt++) {
                MMA_BF16(acc[mt][nt], a[mt][0].x, a[mt][1].x, a[mt][2].x, a[mt][3].x,
                         b[nt][0].x, b[nt][1].x);   // Ah * Bh
                MMA_BF16(acc[mt][nt], a[mt][0].x, a[mt][1].x, a[mt][2].x, a[mt][3].x,
                         b[nt][0].y, b[nt][1].y);   // Ah * Bl
                MMA_BF16(acc[mt][nt], a[mt][0].y, a[mt][1].y, a[mt][2].y, a[mt][3].y,
                         b[nt][0].x, b[nt][1].x);   // Al * Bh
            }
    }

    // ----------------------------- epilogue --------------------------------
#pragma unroll
    for (int nt = 0; nt < 4; nt++) {
        const int col = n0 + wn * 32 + nt * 8 + (lane & 3) * 2;
        const float b0v = bias[col], b1v = bias[col + 1];
#pragma unroll
        for (int mt = 0; mt < 2; mt++) {
#pragma unroll
            for (int half = 0; half < 2; half++) {
                int m = m0 + wm * 32 + mt * 16 + (lane >> 2) + half * 8;
                float v0 = acc[mt][nt][half * 2 + 0] + b0v;
                float v1 = acc[mt][nt][half * 2 + 1] + b1v;
                if (Epi == EPI_GELU) {
                    v0 = 0.5f * v0 * (1.f + erff(v0 * 0.70710678118654752f));
                    v1 = 0.5f * v1 * (1.f + erff(v1 * 0.70710678118654752f));
                }
                int outrow = (Epi == EPI_RES_SCATTER) ? map_shift_row(m) : m;
                float* cp = C + (size_t)outrow * Ndim + col;
                if (Epi == EPI_RES_SCATTER || Epi == EPI_RES_DIRECT) {
                    float2 rr = *reinterpret_cast<const float2*>(
                        res + (size_t)outrow * Ndim + col);
                    v0 += rr.x; v1 += rr.y;
                }
                *reinterpret_cast<float2*>(cp) = make_float2(v0, v1);
            }
        }
    }
}

// --------------------------- Attention -------------------------------------
// one 64-thread block per (window, head); thread = query row n
__global__ void __launch_bounds__(64)
attn_kernel(const float* __restrict__ qkv, const float* __restrict__ rpb,
            float* __restrict__ out)
{
    __shared__ float Ksm[64][36];
    __shared__ float Vsm[64][36];
    __shared__ float bsm[1350];      // 225 * 6

    const int head = blockIdx.x % HEADS;
    const int win  = blockIdx.x / HEADS;
    const int n    = threadIdx.x;

    for (int i = n; i < 1350; i += 64) bsm[i] = rpb[i];

    const float* base = qkv + (size_t)win * 64 * QKVDIM;
    const float* qp = base + n * QKVDIM + head * HD;
    const float* kp = qp + CDIM;
    const float* vp = qp + 2 * CDIM;

    float q[32];
#pragma unroll
    for (int d4 = 0; d4 < 8; d4++) {
        float4 kv = *reinterpret_cast<const float4*>(kp + d4 * 4);
        Ksm[n][d4 * 4 + 0] = kv.x; Ksm[n][d4 * 4 + 1] = kv.y;
        Ksm[n][d4 * 4 + 2] = kv.z; Ksm[n][d4 * 4 + 3] = kv.w;
        float4 vv = *reinterpret_cast<const float4*>(vp + d4 * 4);
        Vsm[n][d4 * 4 + 0] = vv.x; Vsm[n][d4 * 4 + 1] = vv.y;
        Vsm[n][d4 * 4 + 2] = vv.z; Vsm[n][d4 * 4 + 3] = vv.w;
        float4 qq = *reinterpret_cast<const float4*>(qp + d4 * 4);
        q[d4 * 4 + 0] = qq.x * SCALE; q[d4 * 4 + 1] = qq.y * SCALE;
        q[d4 * 4 + 2] = qq.z * SCALE; q[d4 * 4 + 3] = qq.w * SCALE;
    }
    __syncthreads();

    const int wi = win & 255, wh = wi >> 4, ww = wi & 15;
    const int i1 = n >> 3, j1 = n & 7;
    const int rh1 = (wh == 15) ? ((i1 < 4) ? 1 : 2) : 0;
    const int rw1 = (ww == 15) ? ((j1 < 4) ? 1 : 2) : 0;

    float s[64];
#pragma unroll
    for (int m = 0; m < 64; m++) {
        float dot = 0.f;
#pragma unroll
        for (int d4 = 0; d4 < 8; d4++) {
            float4 kk = *reinterpret_cast<const float4*>(&Ksm[m][d4 * 4]);
            dot = fmaf(q[d4 * 4 + 0], kk.x, dot);
            dot = fmaf(q[d4 * 4 + 1], kk.y, dot);
            dot = fmaf(q[d4 * 4 + 2], kk.z, dot);
            dot = fmaf(q[d4 * 4 + 3], kk.w, dot);
        }
        const int i2 = m >> 3, j2 = m & 7;
        float bias = bsm[((i1 - i2 + 7) * 15 + (j1 - j2 + 7)) * HEADS + head];
        const int rh2 = (wh == 15) ? ((i2 < 4) ? 1 : 2) : 0;
        const int rw2 = (ww == 15) ? ((j2 < 4) ? 1 : 2) : 0;
        float msk = (rh1 == rh2 && rw1 == rw2) ? 0.f : -100.f;
        s[m] = dot + bias + msk;
    }

    float mx = -1e30f;
#pragma unroll
    for (int m = 0; m < 64; m++) mx = fmaxf(mx, s[m]);
    float sum = 0.f;
#pragma unroll
    for (int m = 0; m < 64; m++) { s[m] = __expf(s[m] - mx); sum += s[m]; }
    float inv = 1.f / sum;

    float o[32] = {};
#pragma unroll
    for (int m = 0; m < 64; m++) {
        float p = s[m] * inv;
#pragma unroll
        for (int d4 = 0; d4 < 8; d4++) {
            float4 vv = *reinterpret_cast<const float4*>(&Vsm[m][d4 * 4]);
            o[d4 * 4 + 0] = fmaf(p, vv.x, o[d4 * 4 + 0]);
            o[d4 * 4 + 1] = fmaf(p, vv.y, o[d4 * 4 + 1]);
            o[d4 * 4 + 2] = fmaf(p, vv.z, o[d4 * 4 + 2]);
            o[d4 * 4 + 3] = fmaf(p, vv.w, o[d4 * 4 + 3]);
        }
    }

    float* op = out + (size_t)(win * 64 + n) * CDIM + head * HD;
#pragma unroll
    for (int d4 = 0; d4 < 8; d4++)
        *reinterpret_cast<float4*>(op + d4 * 4) =
            make_float4(o[d4 * 4 + 0], o[d4 * 4 + 1], o[d4 * 4 + 2], o[d4 * 4 + 3]);
}

// ---------------------------------------------------------------------------
extern "C" void kernel_launch(void* const* d_in, const int* in_sizes, int n_in,
                              void* d_out, int out_size)
{
    const float* x       = (const float*)d_in[0];
    const float* norm1_g = (const float*)d_in[1];
    const float* norm1_b = (const float*)d_in[2];
    const float* qkv_w   = (const float*)d_in[3];
    const float* qkv_b   = (const float*)d_in[4];
    const float* proj_w  = (const float*)d_in[5];
    const float* proj_b  = (const float*)d_in[6];
    const float* rpb     = (const float*)d_in[7];
    const float* norm2_g = (const float*)d_in[8];
    const float* norm2_b = (const float*)d_in[9];
    const float* fc1_w   = (const float*)d_in[10];
    const float* fc1_b   = (const float*)d_in[11];
    const float* fc2_w   = (const float*)d_in[12];
    const float* fc2_b   = (const float*)d_in[13];
    float* out = (float*)d_out;

    float *p_ln, *p_qkv, *p_attn, *p_h, *p_m1;
    cudaGetSymbolAddress((void**)&p_ln,   g_ln);
    cudaGetSymbolAddress((void**)&p_qkv,  g_qkv);
    cudaGetSymbolAddress((void**)&p_attn, g_attn);
    cudaGetSymbolAddress((void**)&p_h,    g_h);
    cudaGetSymbolAddress((void**)&p_m1,   g_m1);

    const dim3 gemmBlk(256);
    const dim3 gridQKV(QKVDIM / 64, TOKENS / 128);
    const dim3 gridC  (CDIM   / 64, TOKENS / 128);
    const dim3 gridM  (MLPDIM / 64, TOKENS / 128);

    // 1. LN1
    ln_kernel<<<TOKENS / 8, 256>>>(x, norm1_g, norm1_b, p_ln);
    // 2. QKV gemm with shifted-window row gather
    gemm_kernel<CDIM, QKVDIM, AM_SHIFT, EPI_BIAS>
        <<<gridQKV, gemmBlk>>>(p_ln, qkv_w, qkv_b, nullptr, p_qkv);
    // 3. windowed attention (bias + shift mask + softmax)
    attn_kernel<<<NWIN * HEADS, 64>>>(p_qkv, rpb, p_attn);
    // 4. proj gemm; scatter rows back (window reverse + roll) + shortcut residual
    gemm_kernel<CDIM, CDIM, AM_DIRECT, EPI_RES_SCATTER>
        <<<gridC, gemmBlk>>>(p_attn, proj_w, proj_b, x, p_h);
    // 5. LN2
    ln_kernel<<<TOKENS / 8, 256>>>(p_h, norm2_g, norm2_b, p_ln);
    // 6. FC1 + exact GELU
    gemm_kernel<CDIM, MLPDIM, AM_DIRECT, EPI_GELU>
        <<<gridM, gemmBlk>>>(p_ln, fc1_w, fc1_b, nullptr, p_m1);
    // 7. FC2 + residual h  -> d_out
    gemm_kernel<MLPDIM, CDIM, AM_DIRECT, EPI_RES_DIRECT>
        <<<gridC, gemmBlk>>>(p_m1, fc2_w, fc2_b, p_h, out);
}

// round 16
// speedup vs baseline: 1.6163x; 1.0466x over previous
#include <cuda_runtime.h>
#include <cuda_bf16.h>
#include <stdint.h>
#include <math.h>

// ---------------------------------------------------------------------------
// SwinIRBlock. GEMMs: mma.sync.m16n8k16.bf16, 3-term hi/lo split.
// Split is computed exactly once per element: weights pre-split per launch,
// activations emitted in split form by their producer kernels. GEMM staging
// is a pure 64-bit copy; mainloop is pure LDS+MMA.
// ---------------------------------------------------------------------------

#define TOKENS   262144          // B*H*W
#define CDIM     192
#define QKVDIM   576
#define MLPDIM   768
#define NWIN     4096            // B * 256
#define HEADS    6
#define HD       32
#define SCALE    0.17677669529663687f   // 32^-0.5

// ---------------- scratch (static device arrays; no allocation) ------------
__device__ uint2 g_ln_s  [ (size_t)TOKENS * 96  ];   // split LN output (k-pairs)
__device__ float g_qkv   [ (size_t)TOKENS * QKVDIM ];
__device__ uint2 g_attn_s[ (size_t)TOKENS * 96  ];   // split attention output
__device__ float g_h     [ (size_t)TOKENS * CDIM ];
__device__ uint2 g_m1_s  [ (size_t)TOKENS * 384 ];   // split gelu(fc1) output
// pre-split weights (uint2 = (hi bf16x2, lo bf16x2) per k-pair)
__device__ uint2 g_qkvw_s[ QKVDIM * 96 ];
__device__ uint2 g_projw_s[ CDIM  * 96 ];
__device__ uint2 g_fc1w_s[ MLPDIM * 96 ];
__device__ uint2 g_fc2w_s[ CDIM  * 384 ];

// window-ordered row r -> token index (cyclic shift -4,-4 gather; same map is
// the scatter for window-reverse + roll(+4,+4))
__device__ __forceinline__ int map_shift_row(int r) {
    int win = r >> 6, n = r & 63;
    int b  = win >> 8;
    int wi = win & 255;
    int wh = wi >> 4, ww = wi & 15;
    int hh = (wh << 3) + (n >> 3);
    int wp = (ww << 3) + (n & 7);
    int hs = (hh + 4) & 127;
    int ws = (wp + 4) & 127;
    return (b << 14) + (hs << 7) + ws;
}

// ------------------------- BF16 split helpers -------------------------------
__device__ __forceinline__ uint2 bf16_split_pair(float v0, float v1) {
    __nv_bfloat162 h = __floats2bfloat162_rn(v0, v1);
    float l0 = v0 - __bfloat162float(h.x);
    float l1 = v1 - __bfloat162float(h.y);
    __nv_bfloat162 l = __floats2bfloat162_rn(l0, l1);
    uint2 r;
    r.x = *reinterpret_cast<unsigned int*>(&h);
    r.y = *reinterpret_cast<unsigned int*>(&l);
    return r;
}

#define MMA_BF16(d, a0, a1, a2, a3, b0, b1)                                   \
    asm volatile("mma.sync.aligned.m16n8k16.row.col.f32.bf16.bf16.f32 "       \
                 "{%0,%1,%2,%3}, {%4,%5,%6,%7}, {%8,%9}, {%0,%1,%2,%3};"      \
                 : "+f"(d[0]), "+f"(d[1]), "+f"(d[2]), "+f"(d[3])             \
                 : "r"(a0), "r"(a1), "r"(a2), "r"(a3), "r"(b0), "r"(b1))

// ----------------------- weight pre-split kernel ----------------------------
__global__ void __launch_bounds__(256)
split_w_kernel(const float* __restrict__ w, uint2* __restrict__ ws, int npairs)
{
    int i = blockIdx.x * 256 + threadIdx.x;
    if (i < npairs) {
        float2 v = *reinterpret_cast<const float2*>(w + 2 * i);
        ws[i] = bf16_split_pair(v.x, v.y);
    }
}

// ---------------------------- LayerNorm -------------------------------------
// reads f32 tokens, writes split uint2 k-pairs
__global__ void __launch_bounds__(256)
ln_kernel(const float* __restrict__ x, const float* __restrict__ g,
          const float* __restrict__ b, uint2* __restrict__ ys)
{
    int token = blockIdx.x * 8 + (threadIdx.x >> 5);
    int lane  = threadIdx.x & 31;
    const float* xp = x + (size_t)token * CDIM;

    float v[6];
    float s = 0.f;
#pragma unroll
    for (int i = 0; i < 3; i++) {
        float2 p = *reinterpret_cast<const float2*>(xp + lane * 2 + i * 64);
        v[2 * i] = p.x; v[2 * i + 1] = p.y; s += p.x + p.y;
    }
#pragma unroll
    for (int o = 16; o > 0; o >>= 1) s += __shfl_xor_sync(0xffffffffu, s, o);
    float mean = s * (1.f / 192.f);

    float s2 = 0.f;
#pragma unroll
    for (int i = 0; i < 6; i++) { float d = v[i] - mean; s2 += d * d; }
#pragma unroll
    for (int o = 16; o > 0; o >>= 1) s2 += __shfl_xor_sync(0xffffffffu, s2, o);
    float rs = rsqrtf(s2 * (1.f / 192.f) + 1e-5f);

    uint2* yp = ys + (size_t)token * 96;
#pragma unroll
    for (int i = 0; i < 3; i++) {
        int c = lane * 2 + i * 64;
        float n0 = (v[2 * i]     - mean) * rs * g[c]     + b[c];
        float n1 = (v[2 * i + 1] - mean) * rs * g[c + 1] + b[c + 1];
        yp[lane + i * 32] = bf16_split_pair(n0, n1);
    }
}

// ------------------------------ GEMM ----------------------------------------
// C[m,n] = sum_k A[row(m),k] * W[n,k] + bias[n]  (+ epilogue)
// A and W are pre-split uint2 planes (row length Kdim/2 k-pairs).
// 256 threads = 8 warps (4x2); BM=128 BN=64, k-step 16; warp tile 32x32.
#define AM_DIRECT 0
#define AM_SHIFT  1
#define EPI_BIAS        0
#define EPI_GELU        1   // writes split uint2 to Cs
#define EPI_RES_SCATTER 2
#define EPI_RES_DIRECT  3

template<int Kdim, int Ndim, int AMap, int Epi>
__global__ void __launch_bounds__(256, 2)
gemm_kernel(const uint2* __restrict__ A, const uint2* __restrict__ W,
            const float* __restrict__ bias, const float* __restrict__ res,
            float* __restrict__ C, uint2* __restrict__ Cs)
{
    constexpr int BM = 128, BN = 64;
    constexpr int NT = Kdim / 16;           // k16 tiles
    constexpr int KP = Kdim / 2;            // k-pairs per row
    __shared__ uint2 Ahl[2][8][BM + 4];     // [buf][k-pair][m]
    __shared__ uint2 Whl[2][8][BN + 4];

    const int tid  = threadIdx.x;
    const int lane = tid & 31;
    const int warp = tid >> 5;
    const int wm   = warp >> 1;
    const int wn   = warp & 1;
    const int m0   = blockIdx.y * BM;
    const int n0   = blockIdx.x * BN;

    // loaders: per k16 tile a row is 4 uint4 (8 k-pairs).
    // A: 128 rows x 4 = 512 uint4 -> 2/thread; W: 64 x 4 = 256 -> 1/thread
    const uint2* aptr[2]; int arow[2], akq[2];
#pragma unroll
    for (int i = 0; i < 2; i++) {
        int f = tid + i * 256;
        arow[i] = f >> 2; akq[i] = f & 3;
        int gr = m0 + arow[i];
        if (AMap == AM_SHIFT) gr = map_shift_row(gr);
        aptr[i] = A + (size_t)gr * KP + akq[i] * 2;
    }
    const int wrow = tid >> 2, wkq = tid & 3;
    const uint2* wptr = W + (size_t)(n0 + wrow) * KP + wkq * 2;

    float acc[2][4][4] = {};

    uint4 av[2], wv;

    // ---- prologue: tile 0 -> buf 0; prefetch tile 1 into regs -------------
#pragma unroll
    for (int i = 0; i < 2; i++) av[i] = *reinterpret_cast<const uint4*>(aptr[i]);
    wv = *reinterpret_cast<const uint4*>(wptr);
#pragma unroll
    for (int i = 0; i < 2; i++) {
        Ahl[0][2 * akq[i] + 0][arow[i]] = make_uint2(av[i].x, av[i].y);
        Ahl[0][2 * akq[i] + 1][arow[i]] = make_uint2(av[i].z, av[i].w);
    }
    Whl[0][2 * wkq + 0][wrow] = make_uint2(wv.x, wv.y);
    Whl[0][2 * wkq + 1][wrow] = make_uint2(wv.z, wv.w);
    if (NT > 1) {
#pragma unroll
        for (int i = 0; i < 2; i++)
            av[i] = *reinterpret_cast<const uint4*>(aptr[i] + 8);
        wv = *reinterpret_cast<const uint4*>(wptr + 8);
    }

    const int g = lane >> 2;       // row-group / B-col within fragment
    const int t = lane & 3;        // k-pair selector

    for (int it = 0; it < NT; ++it) {
        const int cur = it & 1;
        __syncthreads();

        // stage prefetched tile (it+1) into the other buffer (pure copy)
        if (it + 1 < NT) {
            const int nxt = cur ^ 1;
#pragma unroll
            for (int i = 0; i < 2; i++) {
                Ahl[nxt][2 * akq[i] + 0][arow[i]] = make_uint2(av[i].x, av[i].y);
                Ahl[nxt][2 * akq[i] + 1][arow[i]] = make_uint2(av[i].z, av[i].w);
            }
            Whl[nxt][2 * wkq + 0][wrow] = make_uint2(wv.x, wv.y);
            Whl[nxt][2 * wkq + 1][wrow] = make_uint2(wv.z, wv.w);
        }
        // prefetch tile (it+2) into registers
        if (it + 2 < NT) {
            const int kp = (it + 2) * 8;
#pragma unroll
            for (int i = 0; i < 2; i++)
                av[i] = *reinterpret_cast<const uint4*>(aptr[i] + kp);
            wv = *reinterpret_cast<const uint4*>(wptr + kp);
        }

        // ---- compute current buffer: 16 LDS.64 + 24 MMA per warp ----------
        uint2 a[2][4], b[4][2];
#pragma unroll
        for (int mt = 0; mt < 2; mt++) {
            int mb = wm * 32 + mt * 16 + g;
            a[mt][0] = Ahl[cur][t    ][mb];
            a[mt][1] = Ahl[cur][t    ][mb + 8];
            a[mt][2] = Ahl[cur][t + 4][mb];
            a[mt][3] = Ahl[cur][t + 4][mb + 8];
        }
#pragma unroll
        for (int nt = 0; nt < 4; nt++) {
            int nb = wn * 32 + nt * 8 + g;
            b[nt][0] = Whl[cur][t    ][nb];
            b[nt][1] = Whl[cur][t + 4][nb];
        }
#pragma unroll
        for (int mt = 0; mt < 2; mt++)
#pragma unroll
            for (int nt = 0; nt < 4; nt++) {
                MMA_BF16(acc[mt][nt], a[mt][0].x, a[mt][1].x, a[mt][2].x, a[mt][3].x,
                         b[nt][0].x, b[nt][1].x);   // Ah * Bh
                MMA_BF16(acc[mt][nt], a[mt][0].x, a[mt][1].x, a[mt][2].x, a[mt][3].x,
                         b[nt][0].y, b[nt][1].y);   // Ah * Bl
                MMA_BF16(acc[mt][nt], a[mt][0].y, a[mt][1].y, a[mt][2].y, a[mt][3].y,
                         b[nt][0].x, b[nt][1].x);   // Al * Bh
            }
    }

    // ----------------------------- epilogue --------------------------------
#pragma unroll
    for (int nt = 0; nt < 4; nt++) {
        const int col = n0 + wn * 32 + nt * 8 + (lane & 3) * 2;
        const float b0v = bias[col], b1v = bias[col + 1];
#pragma unroll
        for (int mt = 0; mt < 2; mt++) {
#pragma unroll
            for (int half = 0; half < 2; half++) {
                int m = m0 + wm * 32 + mt * 16 + (lane >> 2) + half * 8;
                float v0 = acc[mt][nt][half * 2 + 0] + b0v;
                float v1 = acc[mt][nt][half * 2 + 1] + b1v;
                if (Epi == EPI_GELU) {
                    v0 = 0.5f * v0 * (1.f + erff(v0 * 0.70710678118654752f));
                    v1 = 0.5f * v1 * (1.f + erff(v1 * 0.70710678118654752f));
                    // (v0,v1) is a k-pair of the next GEMM's A: store split
                    Cs[(size_t)m * (Ndim / 2) + (col >> 1)] = bf16_split_pair(v0, v1);
                    continue;
                }
                int outrow = (Epi == EPI_RES_SCATTER) ? map_shift_row(m) : m;
                float* cp = C + (size_t)outrow * Ndim + col;
                if (Epi == EPI_RES_SCATTER || Epi == EPI_RES_DIRECT) {
                    float2 rr = *reinterpret_cast<const float2*>(
                        res + (size_t)outrow * Ndim + col);
                    v0 += rr.x; v1 += rr.y;
                }
                *reinterpret_cast<float2*>(cp) = make_float2(v0, v1);
            }
        }
    }
}

// --------------------------- Attention --------------------------------------
// one 64-thread block per (window, head); thread = query row n.
// Output written in split uint2 form for the proj GEMM.
__global__ void __launch_bounds__(64)
attn_kernel(const float* __restrict__ qkv, const float* __restrict__ rpb,
            uint2* __restrict__ out_s)
{
    __shared__ float Ksm[64][36];
    __shared__ float Vsm[64][36];
    __shared__ float bsm[1350];      // 225 * 6

    const int head = blockIdx.x % HEADS;
    const int win  = blockIdx.x / HEADS;
    const int n    = threadIdx.x;

    for (int i = n; i < 1350; i += 64) bsm[i] = rpb[i];

    const float* base = qkv + (size_t)win * 64 * QKVDIM;
    const float* qp = base + n * QKVDIM + head * HD;
    const float* kp = qp + CDIM;
    const float* vp = qp + 2 * CDIM;

    float q[32];
#pragma unroll
    for (int d4 = 0; d4 < 8; d4++) {
        float4 kv = *reinterpret_cast<const float4*>(kp + d4 * 4);
        Ksm[n][d4 * 4 + 0] = kv.x; Ksm[n][d4 * 4 + 1] = kv.y;
        Ksm[n][d4 * 4 + 2] = kv.z; Ksm[n][d4 * 4 + 3] = kv.w;
        float4 vv = *reinterpret_cast<const float4*>(vp + d4 * 4);
        Vsm[n][d4 * 4 + 0] = vv.x; Vsm[n][d4 * 4 + 1] = vv.y;
        Vsm[n][d4 * 4 + 2] = vv.z; Vsm[n][d4 * 4 + 3] = vv.w;
        float4 qq = *reinterpret_cast<const float4*>(qp + d4 * 4);
        q[d4 * 4 + 0] = qq.x * SCALE; q[d4 * 4 + 1] = qq.y * SCALE;
        q[d4 * 4 + 2] = qq.z * SCALE; q[d4 * 4 + 3] = qq.w * SCALE;
    }
    __syncthreads();

    const int wi = win & 255, wh = wi >> 4, ww = wi & 15;
    const int i1 = n >> 3, j1 = n & 7;
    const int rh1 = (wh == 15) ? ((i1 < 4) ? 1 : 2) : 0;
    const int rw1 = (ww == 15) ? ((j1 < 4) ? 1 : 2) : 0;

    float s[64];
#pragma unroll
    for (int m = 0; m < 64; m++) {
        float dot = 0.f;
#pragma unroll
        for (int d4 = 0; d4 < 8; d4++) {
            float4 kk = *reinterpret_cast<const float4*>(&Ksm[m][d4 * 4]);
            dot = fmaf(q[d4 * 4 + 0], kk.x, dot);
            dot = fmaf(q[d4 * 4 + 1], kk.y, dot);
            dot = fmaf(q[d4 * 4 + 2], kk.z, dot);
            dot = fmaf(q[d4 * 4 + 3], kk.w, dot);
        }
        const int i2 = m >> 3, j2 = m & 7;
        float bias = bsm[((i1 - i2 + 7) * 15 + (j1 - j2 + 7)) * HEADS + head];
        const int rh2 = (wh == 15) ? ((i2 < 4) ? 1 : 2) : 0;
        const int rw2 = (ww == 15) ? ((j2 < 4) ? 1 : 2) : 0;
        float msk = (rh1 == rh2 && rw1 == rw2) ? 0.f : -100.f;
        s[m] = dot + bias + msk;
    }

    float mx = -1e30f;
#pragma unroll
    for (int m = 0; m < 64; m++) mx = fmaxf(mx, s[m]);
    float sum = 0.f;
#pragma unroll
    for (int m = 0; m < 64; m++) { s[m] = __expf(s[m] - mx); sum += s[m]; }
    float inv = 1.f / sum;

    float o[32] = {};
#pragma unroll
    for (int m = 0; m < 64; m++) {
        float p = s[m] * inv;
#pragma unroll
        for (int d4 = 0; d4 < 8; d4++) {
            float4 vv = *reinterpret_cast<const float4*>(&Vsm[m][d4 * 4]);
            o[d4 * 4 + 0] = fmaf(p, vv.x, o[d4 * 4 + 0]);
            o[d4 * 4 + 1] = fmaf(p, vv.y, o[d4 * 4 + 1]);
            o[d4 * 4 + 2] = fmaf(p, vv.z, o[d4 * 4 + 2]);
            o[d4 * 4 + 3] = fmaf(p, vv.w, o[d4 * 4 + 3]);
        }
    }

    uint2* op = out_s + (size_t)(win * 64 + n) * 96 + head * 16;
#pragma unroll
    for (int p2 = 0; p2 < 16; p2++)
        op[p2] = bf16_split_pair(o[2 * p2], o[2 * p2 + 1]);
}

// ---------------------------------------------------------------------------
extern "C" void kernel_launch(void* const* d_in, const int* in_sizes, int n_in,
                              void* d_out, int out_size)
{
    const float* x       = (const float*)d_in[0];
    const float* norm1_g = (const float*)d_in[1];
    const float* norm1_b = (const float*)d_in[2];
    const float* qkv_w   = (const float*)d_in[3];
    const float* qkv_b   = (const float*)d_in[4];
    const float* proj_w  = (const float*)d_in[5];
    const float* proj_b  = (const float*)d_in[6];
    const float* rpb     = (const float*)d_in[7];
    const float* norm2_g = (const float*)d_in[8];
    const float* norm2_b = (const float*)d_in[9];
    const float* fc1_w   = (const float*)d_in[10];
    const float* fc1_b   = (const float*)d_in[11];
    const float* fc2_w   = (const float*)d_in[12];
    const float* fc2_b   = (const float*)d_in[13];
    float* out = (float*)d_out;

    uint2 *p_ln_s, *p_attn_s, *p_m1_s, *p_qkvw, *p_projw, *p_fc1w, *p_fc2w;
    float *p_qkv, *p_h;
    cudaGetSymbolAddress((void**)&p_ln_s,   g_ln_s);
    cudaGetSymbolAddress((void**)&p_qkv,    g_qkv);
    cudaGetSymbolAddress((void**)&p_attn_s, g_attn_s);
    cudaGetSymbolAddress((void**)&p_h,      g_h);
    cudaGetSymbolAddress((void**)&p_m1_s,   g_m1_s);
    cudaGetSymbolAddress((void**)&p_qkvw,   g_qkvw_s);
    cudaGetSymbolAddress((void**)&p_projw,  g_projw_s);
    cudaGetSymbolAddress((void**)&p_fc1w,   g_fc1w_s);
    cudaGetSymbolAddress((void**)&p_fc2w,   g_fc2w_s);

    // 0. pre-split weights (once per call; tiny)
    split_w_kernel<<<(QKVDIM * 96 + 255) / 256, 256>>>(qkv_w,  p_qkvw,  QKVDIM * 96);
    split_w_kernel<<<(CDIM   * 96 + 255) / 256, 256>>>(proj_w, p_projw, CDIM   * 96);
    split_w_kernel<<<(MLPDIM * 96 + 255) / 256, 256>>>(fc1_w,  p_fc1w,  MLPDIM * 96);
    split_w_kernel<<<(CDIM  * 384 + 255) / 256, 256>>>(fc2_w,  p_fc2w,  CDIM  * 384);

    const dim3 gemmBlk(256);
    const dim3 gridQKV(QKVDIM / 64, TOKENS / 128);
    const dim3 gridC  (CDIM   / 64, TOKENS / 128);
    const dim3 gridM  (MLPDIM / 64, TOKENS / 128);

    // 1. LN1 -> split
    ln_kernel<<<TOKENS / 8, 256>>>(x, norm1_g, norm1_b, p_ln_s);
    // 2. QKV gemm with shifted-window row gather
    gemm_kernel<CDIM, QKVDIM, AM_SHIFT, EPI_BIAS>
        <<<gridQKV, gemmBlk>>>(p_ln_s, p_qkvw, qkv_b, nullptr, p_qkv, nullptr);
    // 3. windowed attention -> split output
    attn_kernel<<<NWIN * HEADS, 64>>>(p_qkv, rpb, p_attn_s);
    // 4. proj gemm; scatter rows back + shortcut residual
    gemm_kernel<CDIM, CDIM, AM_DIRECT, EPI_RES_SCATTER>
        <<<gridC, gemmBlk>>>(p_attn_s, p_projw, proj_b, x, p_h, nullptr);
    // 5. LN2 -> split
    ln_kernel<<<TOKENS / 8, 256>>>(p_h, norm2_g, norm2_b, p_ln_s);
    // 6. FC1 + exact GELU -> split output
    gemm_kernel<CDIM, MLPDIM, AM_DIRECT, EPI_GELU>
        <<<gridM, gemmBlk>>>(p_ln_s, p_fc1w, fc1_b, nullptr, nullptr, p_m1_s);
    // 7. FC2 + residual h -> d_out
    gemm_kernel<MLPDIM, CDIM, AM_DIRECT, EPI_RES_DIRECT>
        <<<gridC, gemmBlk>>>(p_m1_s, p_fc2w, fc2_b, p_h, out, nullptr);
}